// round 5
// baseline (speedup 1.0000x reference)
#include <cuda_runtime.h>

#define HW   128
#define IMG  (HW*HW)
#define NB   64

typedef unsigned long long u64;

// Scratch buffers (allocation-free rule: __device__ globals)
__device__ float g_bufA[(size_t)NB * 22 * IMG];  // 22-ch concat buffer; x lives in ch 12..21
__device__ float g_bufB[(size_t)NB * 24 * IMG];
__device__ float g_bufC[(size_t)NB * 24 * IMG];

__device__ __forceinline__ u64 fma2(u64 a, u64 b, u64 c) {
    u64 d;
    asm("fma.rn.f32x2 %0, %1, %2, %3;" : "=l"(d) : "l"(a), "l"(b), "l"(c));
    return d;
}
__device__ __forceinline__ float2 unpack2(u64 v) {
    unsigned int lo, hi;
    asm("mov.b64 {%0, %1}, %2;" : "=r"(lo), "=r"(hi) : "l"(v));
    return make_float2(__uint_as_float(lo), __uint_as_float(hi));
}

// ---------------------------------------------------------------------------
// Fused per-sample 3x3 conv + eval-BN + ReLU, 12 output channels per CTA.
// 128 threads, tile 64x8, T=4 rows/thread.
// Input tile staged in smem with every pixel DUPLICATED (float2{v,v}) so one
// LDS.64 produces a packed f32x2 operand -- no pack MOVs in the hot loop.
// Input channels chunked by 6; CIN padded to CINP (12 or 24) with zero
// weights/inputs. 24-out layers split into two output halves (NHALF=2).
// ---------------------------------------------------------------------------
template<int CIN, int CINP, int NHALF>
__global__ __launch_bounds__(128, (CINP == 12) ? 6 : 5)
void conv3x3_bn_relu12(const float* __restrict__ in, int in_nch,
                       const float* __restrict__ wflat, int wP, int wbase,
                       const float* __restrict__ gam, const float* __restrict__ bet,
                       const float* __restrict__ mea, const float* __restrict__ varr,
                       int bnoff,
                       float* __restrict__ out, int out_nch)
{
    constexpr int COUT   = 12;
    constexpr int T      = 4;
    constexpr int TILE_X = 64;
    constexpr int TILE_Y = 8;
    constexpr int TXW    = TILE_X + 2;   // 66
    constexpr int TYH    = TILE_Y + 2;   // 10
    constexpr int CHUNK  = 6;
    constexpr int NCH    = CINP / CHUNK; // 2 or 4
    constexpr int NT     = 128;

    extern __shared__ float smem[];
    float* s_in = smem;                            // CHUNK*TYH*TXW float2 (dup pixels)
    float* s_w  = s_in + CHUNK * TYH * TXW * 2;    // CINP * 9 * 12 (layout [i][k][o])
    float* s_sc = s_w + CINP * 9 * COUT;           // 12
    float* s_bi = s_sc + COUT;                     // 12

    const int tid  = threadIdx.x;
    const int b    = blockIdx.z;
    const int half   = blockIdx.x & (NHALF - 1);
    const int ochoff = half * 12;
    const int gx0  = (blockIdx.x / NHALF) * TILE_X;
    const int gy0  = blockIdx.y * TILE_Y;

    // --- load + repack weights: [o][i][k] (gmem) -> [i][k][o] (smem), pad i>=CIN with 0 ---
    const float* wsrc = wflat + (size_t)b * wP + wbase + (size_t)ochoff * CIN * 9;
    for (int idx = tid; idx < CINP * 9 * COUT; idx += NT) {
        int o = idx % COUT;
        int r = idx / COUT;
        int k = r % 9;
        int i = r / 9;
        s_w[idx] = (i < CIN) ? wsrc[(o * CIN + i) * 9 + k] : 0.f;
    }
    if (tid < COUT) {
        int c = bnoff + ochoff + tid;
        float g = gam[c], bb = bet[c], m = mea[c], v = varr[c];
        float inv = g * rsqrtf(v + 1e-5f);
        s_sc[tid] = inv;
        s_bi[tid] = bb - m * inv;
    }

    const int lane = tid & 31;
    const int warp = tid >> 5;
    const int xl   = (warp & 1) * 32 + lane;   // 0..63
    const int y0   = (warp >> 1) * T;          // 0,4

    u64 acc[T][6];
    #pragma unroll
    for (int p = 0; p < T; p++)
        #pragma unroll
        for (int u = 0; u < 6; u++) acc[p][u] = 0ull;

    const ulonglong2* w16   = (const ulonglong2*)s_w;   // 3 vec per (i,k)
    const u64*        s64   = (const u64*)s_in;         // dup-pixel view
    float2*           s_in2 = (float2*)s_in;
    const float*      inb   = in + (size_t)b * in_nch * IMG;

    for (int ch = 0; ch < NCH; ch++) {
        __syncthreads();
        // --- stage CHUNK channels (halo, zero-padded, DUPLICATED) into smem ---
        #pragma unroll 1
        for (int idx = tid; idx < CHUNK * TYH * TXW; idx += NT) {
            int c = idx % TXW;
            int r = (idx / TXW) % TYH;
            int i = idx / (TXW * TYH);
            int ii = ch * CHUNK + i;
            int gy = gy0 - 1 + r, gx = gx0 - 1 + c;
            float v = 0.f;
            if (ii < CIN && (unsigned)gy < HW && (unsigned)gx < HW)
                v = inb[(size_t)ii * IMG + gy * HW + gx];
            s_in2[idx] = make_float2(v, v);
        }
        __syncthreads();

        #pragma unroll 2
        for (int i = 0; i < CHUNK; i++) {
            const int ii  = ch * CHUNK + i;
            const int ib  = (i * TYH + y0) * TXW + xl;   // dup-element index
            #pragma unroll
            for (int kx = 0; kx < 3; kx++) {
                u64 vr[T + 2];
                #pragma unroll
                for (int r = 0; r < T + 2; r++)
                    vr[r] = s64[ib + r * TXW + kx];      // LDS.64: packed (v,v)
                #pragma unroll
                for (int ky = 0; ky < 3; ky++) {
                    const ulonglong2* wp = &w16[(size_t)(ii * 9 + ky * 3 + kx) * 3];
                    #pragma unroll
                    for (int v = 0; v < 3; v++) {
                        ulonglong2 w = wp[v];            // 2 packed oc-pairs
                        #pragma unroll
                        for (int p = 0; p < T; p++) {
                            acc[p][2 * v]     = fma2(vr[p + ky], w.x, acc[p][2 * v]);
                            acc[p][2 * v + 1] = fma2(vr[p + ky], w.y, acc[p][2 * v + 1]);
                        }
                    }
                }
            }
        }
    }

    // --- epilogue: BN (eval) + ReLU + store ---
    float* ob = out + (size_t)b * out_nch * IMG + (size_t)ochoff * IMG;
    #pragma unroll
    for (int p = 0; p < T; p++) {
        const int y = gy0 + y0 + p;
        const int x = gx0 + xl;
        float* op = ob + y * HW + x;
        #pragma unroll
        for (int u = 0; u < 6; u++) {
            float2 a = unpack2(acc[p][u]);
            int o0 = 2 * u, o1 = 2 * u + 1;
            float r0 = fmaf(a.x, s_sc[o0], s_bi[o0]);
            float r1 = fmaf(a.y, s_sc[o1], s_bi[o1]);
            op[(size_t)o0 * IMG] = fmaxf(r0, 0.f);
            op[(size_t)o1 * IMG] = fmaxf(r1, 0.f);
        }
    }
}

// ---------------------------------------------------------------------------
// Copy x into channels 12..21 of bufA (makes the dense-skip concat free).
// ---------------------------------------------------------------------------
__global__ void copy_x_kernel(const float* __restrict__ x, float* __restrict__ bufA)
{
    size_t idx = (size_t)blockIdx.x * blockDim.x + threadIdx.x;
    const size_t total = (size_t)NB * 10 * IMG;
    if (idx < total) {
        int p = (int)(idx % IMG);
        int c = (int)((idx / IMG) % 10);
        int b = (int)(idx / ((size_t)IMG * 10));
        bufA[((size_t)b * 22 + 12 + c) * IMG + p] = x[idx];
    }
}

// ---------------------------------------------------------------------------
// Final per-sample 1x1 conv: [B,22,H,W] x [B,11,22] -> [B,11,H,W]
// ---------------------------------------------------------------------------
__global__ __launch_bounds__(256)
void conv1x1_kernel(const float* __restrict__ in, const float* __restrict__ w4,
                    float* __restrict__ out)
{
    __shared__ float s_w[11 * 22];
    const int b   = blockIdx.y;
    const int tid = threadIdx.x;
    if (tid < 242) s_w[tid] = w4[b * 242 + tid];
    __syncthreads();

    const int p0 = blockIdx.x * (256 * 4) + tid;
    const float* inb = in  + (size_t)b * 22 * IMG;
    float*       ob  = out + (size_t)b * 11 * IMG;

    float acc[4][11];
    #pragma unroll
    for (int q = 0; q < 4; q++)
        #pragma unroll
        for (int o = 0; o < 11; o++) acc[q][o] = 0.f;

    #pragma unroll 2
    for (int i = 0; i < 22; i++) {
        float v[4];
        #pragma unroll
        for (int q = 0; q < 4; q++) v[q] = inb[(size_t)i * IMG + p0 + q * 256];
        #pragma unroll
        for (int o = 0; o < 11; o++) {
            float w = s_w[o * 22 + i];
            #pragma unroll
            for (int q = 0; q < 4; q++) acc[q][o] = fmaf(v[q], w, acc[q][o]);
        }
    }
    #pragma unroll
    for (int o = 0; o < 11; o++)
        #pragma unroll
        for (int q = 0; q < 4; q++)
            ob[(size_t)o * IMG + p0 + q * 256] = acc[q][o];
}

// ---------------------------------------------------------------------------

static int smem_bytes(int cinp) {
    // dup input tile (CHUNK=6) + weights + BN consts
    return (6 * 10 * 66 * 2 + cinp * 9 * 12 + 24) * 4;
}

extern "C" void kernel_launch(void* const* d_in, const int* in_sizes, int n_in,
                              void* d_out, int out_size)
{
    const float* x   = (const float*)d_in[0];
    const float* w1  = (const float*)d_in[1];
    const float* w2  = (const float*)d_in[2];
    const float* w3  = (const float*)d_in[3];
    const float* w4  = (const float*)d_in[4];
    const float* gam = (const float*)d_in[5];
    const float* bet = (const float*)d_in[6];
    const float* mea = (const float*)d_in[7];
    const float* var = (const float*)d_in[8];
    float* out = (float*)d_out;

    float *bufA, *bufB, *bufC;
    cudaGetSymbolAddress((void**)&bufA, g_bufA);
    cudaGetSymbolAddress((void**)&bufB, g_bufB);
    cudaGetSymbolAddress((void**)&bufC, g_bufC);

    // opt-in to >48KB dynamic smem (idempotent; host-side, capture-safe)
    cudaFuncSetAttribute(conv3x3_bn_relu12<10,12,1>, cudaFuncAttributeMaxDynamicSharedMemorySize, smem_bytes(12));
    cudaFuncSetAttribute(conv3x3_bn_relu12<12,12,1>, cudaFuncAttributeMaxDynamicSharedMemorySize, smem_bytes(12));
    cudaFuncSetAttribute(conv3x3_bn_relu12<22,24,2>, cudaFuncAttributeMaxDynamicSharedMemorySize, smem_bytes(24));
    cudaFuncSetAttribute(conv3x3_bn_relu12<24,24,2>, cudaFuncAttributeMaxDynamicSharedMemorySize, smem_bytes(24));
    cudaFuncSetAttribute(conv3x3_bn_relu12<24,24,1>, cudaFuncAttributeMaxDynamicSharedMemorySize, smem_bytes(24));

    const dim3 g1(2, 16, NB);   // NHALF=1: 2 x-tiles, 16 y-tiles
    const dim3 g2(4, 16, NB);   // NHALF=2: 2 x-tiles * 2 output halves

    // x -> bufA channels 12..21 (skip-concat source, written once per launch)
    copy_x_kernel<<<(NB * 10 * IMG + 255) / 256, 256>>>(x, bufA);

    // ---- stage 1 ----  (BN offsets: 0,12,24)
    conv3x3_bn_relu12<10,12,1><<<g1, 128, smem_bytes(12)>>>(x,    10, w1, 3672,    0, gam,bet,mea,var,   0, bufB, 24);
    conv3x3_bn_relu12<12,12,1><<<g1, 128, smem_bytes(12)>>>(bufB, 24, w1, 3672, 1080, gam,bet,mea,var,  12, bufC, 24);
    conv3x3_bn_relu12<12,12,1><<<g1, 128, smem_bytes(12)>>>(bufC, 24, w1, 3672, 2376, gam,bet,mea,var,  24, bufA, 22);
    // ---- stage 2 ----  (BN offsets: 36,60,84)
    conv3x3_bn_relu12<22,24,2><<<g2, 128, smem_bytes(24)>>>(bufA, 22, w2, 12528,    0, gam,bet,mea,var,  36, bufB, 24);
    conv3x3_bn_relu12<24,24,2><<<g2, 128, smem_bytes(24)>>>(bufB, 24, w2, 12528, 4752, gam,bet,mea,var,  60, bufC, 24);
    conv3x3_bn_relu12<24,24,1><<<g1, 128, smem_bytes(24)>>>(bufC, 24, w2, 12528, 9936, gam,bet,mea,var,  84, bufA, 22);
    // ---- stage 3 ----  (BN offsets: 96,120,144)
    conv3x3_bn_relu12<22,24,2><<<g2, 128, smem_bytes(24)>>>(bufA, 22, w3, 12528,    0, gam,bet,mea,var,  96, bufB, 24);
    conv3x3_bn_relu12<24,24,2><<<g2, 128, smem_bytes(24)>>>(bufB, 24, w3, 12528, 4752, gam,bet,mea,var, 120, bufC, 24);
    conv3x3_bn_relu12<24,24,1><<<g1, 128, smem_bytes(24)>>>(bufC, 24, w3, 12528, 9936, gam,bet,mea,var, 144, bufA, 22);
    // ---- stage 4: 1x1 predictor ----
    conv1x1_kernel<<<dim3(IMG / (256 * 4), NB), 256>>>(bufA, w4, out);
}